// round 14
// baseline (speedup 1.0000x reference)
#include <cuda_runtime.h>
#include <cuda_fp16.h>
#include <cstdint>

// Problem constants (fixed by the reference)
#define NNODES 50000
#define NREL   8
#define DIM    128
#define NEDGES 800000
#define NZ     9                       // z=0: root path, z=1..8: relations 0..7
#define MTILE  128
#define SEG    (NREL * NNODES)         // 400000
#define NSCAN_BLK ((SEG + 511) / 512)  // 782
#define NVEC   (NREL + 1)              // 8 relation sums + 1 node sum

// row-block pipeline split (multiple of 128 and of 8)
#define H0N 25088
#define H1N (NNODES - H0N)             // 24912
#define G0B (H0N / MTILE)              // 196
#define G1B ((H1N + MTILE - 1) / MTILE) // 195

// K = 9*128 = 1152, chunked by BK=64 halves (32 u32). Row stride 36 u32 (pad 4):
// ldmatrix 8 rows spaced 36 u32 -> start banks {0,4,...,28}, 4 banks/row -> conflict-free.
#define NCHUNK 18
#define CSTR   36
#define A_CH   (MTILE * CSTR)          // 4608 u32 = 18432 B
#define GEMM_SMEM (4 * A_CH * 4)       // A[2] + B[2] = 73728 B

// layer-2 edge-centric reduction geometry
#define E2_BLOCKS 1184
#define E2_WARPS  (E2_BLOCKS * 8)                  // 9472
#define EPW       ((NEDGES + E2_WARPS - 1) / E2_WARPS)  // 85

// ---------------- scratch (static device globals; no allocation) ----------------
__device__ __half g_M16[(size_t)NREL * NNODES * DIM]; // layer-1 per-relation means (fp16)
__device__ __half g_A16[(size_t)NNODES * DIM];        // layer-1 input (fp16)
__device__ __half g_B16[(size_t)NNODES * DIM];        // layer-1 output (fp16)
__device__ __half g_WH[NZ * DIM * DIM];               // layer-1 weights [z][n][k], z=0 root
__device__ float  g_vs[NVEC * DIM];                   // layer-2 reduced vectors (fp32)
__device__ int    g_cnt[SEG];
__device__ int    g_incl[SEG];
__device__ int    g_off[SEG + 1];
__device__ int    g_cursor[SEG];
__device__ float  g_inv[SEG];
__device__ int    g_binh[NEDGES];
__device__ float  g_binw[NEDGES];
__device__ int    g_bsum[1024];

// ---------------- helpers ----------------
__device__ __forceinline__ void mma_f16(float* c, const uint32_t* a, const uint32_t* b) {
    asm volatile(
        "mma.sync.aligned.m16n8k16.row.col.f32.f16.f16.f32 "
        "{%0,%1,%2,%3}, {%4,%5,%6,%7}, {%8,%9}, {%0,%1,%2,%3};"
        : "+f"(c[0]), "+f"(c[1]), "+f"(c[2]), "+f"(c[3])
        : "r"(a[0]), "r"(a[1]), "r"(a[2]), "r"(a[3]), "r"(b[0]), "r"(b[1]));
}
__device__ __forceinline__ void ldsm_x4(uint32_t& r0, uint32_t& r1, uint32_t& r2,
                                        uint32_t& r3, uint32_t addr) {
    asm volatile("ldmatrix.sync.aligned.m8n8.x4.shared.b16 {%0,%1,%2,%3}, [%4];"
                 : "=r"(r0), "=r"(r1), "=r"(r2), "=r"(r3) : "r"(addr));
}
__device__ __forceinline__ void cp_async16(uint32_t daddr, const void* src, int srcbytes) {
    asm volatile("cp.async.cg.shared.global [%0], [%1], 16, %2;"
                 :: "r"(daddr), "l"(src), "r"(srcbytes));
}
#define CP_COMMIT() asm volatile("cp.async.commit_group;" ::: "memory")
#define CP_WAIT1()  asm volatile("cp.async.wait_group 1;" ::: "memory")
#define CP_WAIT0()  asm volatile("cp.async.wait_group 0;" ::: "memory")

// ---------------- setup / binning kernels ----------------
__global__ void k_zero_cnt(int* __restrict__ cnt, int n) {
    int i = blockIdx.x * blockDim.x + threadIdx.x;
    if (i < n) cnt[i] = 0;
}
__global__ void k_count(const int* __restrict__ r, const int* __restrict__ t,
                        int* __restrict__ cnt, int E) {
    int e = blockIdx.x * blockDim.x + threadIdx.x;
    if (e < E) atomicAdd(&cnt[r[e] * NNODES + t[e]], 1);
}
__global__ void k_scan1(const int* __restrict__ cnt, int* __restrict__ incl,
                        int* __restrict__ bsum, int n) {
    __shared__ int sm[512];
    int tid = threadIdx.x;
    int gid = blockIdx.x * 512 + tid;
    sm[tid] = (gid < n) ? cnt[gid] : 0;
    __syncthreads();
#pragma unroll
    for (int d = 1; d < 512; d <<= 1) {
        int add = (tid >= d) ? sm[tid - d] : 0;
        __syncthreads();
        sm[tid] += add;
        __syncthreads();
    }
    if (gid < n) incl[gid] = sm[tid];
    if (tid == 511) bsum[blockIdx.x] = sm[511];
}
__global__ void k_scan2(int* __restrict__ bsum, int nb) {
    __shared__ int sm[1024];
    int tid = threadIdx.x;
    sm[tid] = (tid < nb) ? bsum[tid] : 0;
    __syncthreads();
#pragma unroll
    for (int d = 1; d < 1024; d <<= 1) {
        int add = (tid >= d) ? sm[tid - d] : 0;
        __syncthreads();
        sm[tid] += add;
        __syncthreads();
    }
    if (tid < nb) bsum[tid] = sm[tid];
}
__global__ void k_scan3(const int* __restrict__ cnt, const int* __restrict__ incl,
                        const int* __restrict__ bsum, int* __restrict__ off,
                        int* __restrict__ cursor, float* __restrict__ inv, int n) {
    int gid = blockIdx.x * 512 + threadIdx.x;
    if (gid >= n) return;
    int base = (blockIdx.x > 0) ? bsum[blockIdx.x - 1] : 0;
    int ex = base + incl[gid] - cnt[gid];
    off[gid] = ex;
    cursor[gid] = ex;
    inv[gid] = 1.0f / fmaxf((float)cnt[gid], 1.0f);
    if (gid == n - 1) off[n] = base + incl[gid];
}
__global__ void k_bin(const int* __restrict__ h, const int* __restrict__ r,
                      const int* __restrict__ t, int* __restrict__ cursor,
                      const float* __restrict__ inv, int* __restrict__ binh,
                      float* __restrict__ binw, int E) {
    int e = blockIdx.x * blockDim.x + threadIdx.x;
    if (e >= E) return;
    int seg = r[e] * NNODES + t[e];
    int pos = atomicAdd(&cursor[seg], 1);
    binh[pos] = h[e];
    binw[pos] = inv[seg];
}

// WH layer-1 only: [z][n][k]; z=0 -> root1, z>=1 -> W1[z-1]; transposed + fp16
__global__ void k_wt1(const float* __restrict__ W1, const float* __restrict__ root1,
                      __half* __restrict__ dst) {
    int idx = blockIdx.x * blockDim.x + threadIdx.x;
    if (idx >= NZ * DIM * DIM) return;
    int z = idx >> 14;
    int rem = idx & 16383;
    int n = rem >> 7, k = rem & 127;
    const float* src = (z == 0) ? root1 : (W1 + ((size_t)(z - 1) << 14));
    dst[idx] = __float2half_rn(src[k * DIM + n]);
}

__global__ void k_cvt16(const float2* __restrict__ in, uint32_t* __restrict__ out, int n2) {
    int i = blockIdx.x * blockDim.x + threadIdx.x;
    if (i < n2) {
        float2 v = in[i];
        __half2 hv = __floats2half2_rn(v.x, v.y);
        out[i] = *(uint32_t*)&hv;
    }
}

__global__ void k_zero_vs(float* __restrict__ vs) {
    int i = blockIdx.x * blockDim.x + threadIdx.x;
    if (i < NVEC * DIM) vs[i] = 0.0f;
}

// ---------------- layer-1 aggregate-first: M16[r][t] = mean over seg(r,t) of X16[h] ----------------
// t0: node-range base for row-block pipelining.
__global__ __launch_bounds__(256) void k_aggF(
    const __half* __restrict__ X16, const int* __restrict__ off,
    const int* __restrict__ binh, __half* __restrict__ M16, int t0)
{
    const int wid = threadIdx.x >> 5;
    const int lane = threadIdx.x & 31;
    const int t = t0 + blockIdx.x * 8 + wid;   // ranges are multiples of 8

#pragma unroll
    for (int rr = 0; rr < NREL; rr++) {
        int seg = rr * NNODES + t;
        int s = __ldg(&off[seg]);
        int e = __ldg(&off[seg + 1]);
        float4 sum = make_float4(0.f, 0.f, 0.f, 0.f);
        if (e > s) {
            for (int i = s; i < e; i++) {
                int hh = __ldg(&binh[i]);
                uint2 v = ((const uint2*)(X16 + (size_t)hh * DIM))[lane];
                __half2* hp = (__half2*)&v;
                float2 f0 = __half22float2(hp[0]);
                float2 f1 = __half22float2(hp[1]);
                sum.x += f0.x; sum.y += f0.y; sum.z += f1.x; sum.w += f1.y;
            }
            float w = 1.0f / (float)(e - s);
            sum.x *= w; sum.y *= w; sum.z *= w; sum.w *= w;
        }
        __half2 h0 = __floats2half2_rn(sum.x, sum.y);
        __half2 h1 = __floats2half2_rn(sum.z, sum.w);
        uint2 o;
        o.x = *(uint32_t*)&h0;
        o.y = *(uint32_t*)&h1;
        ((uint2*)(M16 + (size_t)seg * DIM))[lane] = o;
    }
}

// ---------------- layer-1 fused K=1152 GEMM: B16 = relu([X | M_1..M_8] @ WH + b1) ----------------
// roff: row-block base for pipelined halves.
__global__ __launch_bounds__(256, 2) void k_gemmF(
    const __half* __restrict__ X, const __half* __restrict__ M,
    const __half* __restrict__ WH, const float* __restrict__ bias,
    __half* __restrict__ out16, int Nn, int roff)
{
    extern __shared__ uint32_t smb[];
    uint32_t* As = smb;                 // [2][A_CH]
    uint32_t* Bs = smb + 2 * A_CH;      // [2][A_CH]

    const int tid = threadIdx.x;
    const int wid = tid >> 5;
    const int lane = tid & 31;
    const int g = lane >> 2;
    const int q = lane & 3;
    const int warp_m = wid & 3;
    const int warp_n = wid >> 2;
    const int row0 = roff + blockIdx.x * MTILE;

    const uint32_t abase = (uint32_t)__cvta_generic_to_shared(As);
    const uint32_t bbase = (uint32_t)__cvta_generic_to_shared(Bs);

    auto fill_chunk = [&](int buf, int c) {
        int z = c >> 1, hc = c & 1;
        const __half* srcA = (z == 0) ? X : (M + (size_t)(z - 1) * Nn * DIM);
        const __half* srcB = WH + ((size_t)z << 14) + hc * 64;
        uint32_t ab = abase + (uint32_t)buf * A_CH * 4;
        uint32_t bb = bbase + (uint32_t)buf * A_CH * 4;
#pragma unroll
        for (int l = 0; l < 4; l++) {
            int lin = tid + 256 * l;
            int row = lin >> 3, seg = lin & 7;
            int gr = row0 + row;
            int ok = (gr < Nn) ? 16 : 0;
            int grc = (gr < Nn) ? gr : (Nn - 1);
            cp_async16(ab + (uint32_t)(row * CSTR + seg * 4) * 4,
                       srcA + (size_t)grc * DIM + hc * 64 + seg * 8, ok);
        }
#pragma unroll
        for (int l = 0; l < 4; l++) {
            int lin = tid + 256 * l;
            int row = lin >> 3, seg = lin & 7;
            cp_async16(bb + (uint32_t)(row * CSTR + seg * 4) * 4,
                       srcB + (size_t)row * DIM + seg * 8, 16);
        }
        CP_COMMIT();
    };
    fill_chunk(0, 0);

    const int sub = lane >> 3;
    const int rin = lane & 7;
    uint32_t aAddr[2], bAddr[4];
#pragma unroll
    for (int mt = 0; mt < 2; mt++) {
        int row = warp_m * 32 + mt * 16 + (sub & 1) * 8 + rin;
        aAddr[mt] = abase + (uint32_t)(row * CSTR + (sub >> 1) * 4) * 4;
    }
#pragma unroll
    for (int p = 0; p < 4; p++) {
        int nrow = warp_n * 64 + p * 16 + (sub >> 1) * 8 + rin;
        bAddr[p] = bbase + (uint32_t)(nrow * CSTR + (sub & 1) * 4) * 4;
    }

    float cfrag[2][8][4];
#pragma unroll
    for (int mt = 0; mt < 2; mt++)
#pragma unroll
        for (int nt = 0; nt < 8; nt++)
#pragma unroll
            for (int i = 0; i < 4; i++) cfrag[mt][nt][i] = 0.0f;

#pragma unroll 1
    for (int c = 0; c < NCHUNK; c++) {
        if (c < NCHUNK - 1) { fill_chunk((c + 1) & 1, c + 1); CP_WAIT1(); }
        else                { CP_WAIT0(); }
        __syncthreads();

        const uint32_t boff = (uint32_t)(c & 1) * A_CH * 4;

#pragma unroll
        for (int ks = 0; ks < 4; ks++) {
            const uint32_t koff = boff + (uint32_t)ks * 32;
            uint32_t a[2][4];
            ldsm_x4(a[0][0], a[0][1], a[0][2], a[0][3], aAddr[0] + koff);
            ldsm_x4(a[1][0], a[1][1], a[1][2], a[1][3], aAddr[1] + koff);
            uint32_t b[8][2];
#pragma unroll
            for (int p = 0; p < 4; p++)
                ldsm_x4(b[2 * p][0], b[2 * p][1], b[2 * p + 1][0], b[2 * p + 1][1],
                        bAddr[p] + koff);
#pragma unroll
            for (int mt = 0; mt < 2; mt++)
#pragma unroll
                for (int nt = 0; nt < 8; nt++)
                    mma_f16(cfrag[mt][nt], a[mt], b[nt]);
        }
        __syncthreads();
    }

#pragma unroll
    for (int mt = 0; mt < 2; mt++)
#pragma unroll
        for (int half_ = 0; half_ < 2; half_++) {
            int row = row0 + warp_m * 32 + mt * 16 + half_ * 8 + g;
            if (row >= Nn) continue;
#pragma unroll
            for (int nt = 0; nt < 8; nt++) {
                int col = warp_n * 64 + nt * 8 + 2 * q;
                float vx = cfrag[mt][nt][half_ * 2 + 0] + bias[col];
                float vy = cfrag[mt][nt][half_ * 2 + 1] + bias[col + 1];
                __half2 hv = __floats2half2_rn(fmaxf(vx, 0.f), fmaxf(vy, 0.f));
                *(uint32_t*)&out16[(size_t)row * DIM + col] = *(uint32_t*)&hv;
            }
        }
}

// ---------------- layer-2 edge-centric reduction ----------------
// vs[r] = Σ_edges(rel r) binw[e] * B16[binh[e]];  vs[8] = Σ_t B16[t].
__global__ __launch_bounds__(256) void k_edge2(
    const __half* __restrict__ B16, const int* __restrict__ off,
    const int* __restrict__ binh, const float* __restrict__ binw,
    float* __restrict__ vs)
{
    __shared__ float ssum[NVEC][DIM];
    const int wid = threadIdx.x >> 5;
    const int lane = threadIdx.x & 31;
    const int gw = blockIdx.x * 8 + wid;

    float acc[NVEC][4];
#pragma unroll
    for (int v = 0; v < NVEC; v++)
#pragma unroll
        for (int j = 0; j < 4; j++) acc[v][j] = 0.0f;

    const int e0 = gw * EPW;
    const int e1 = min(e0 + EPW, NEDGES);

#pragma unroll
    for (int rr = 0; rr < NREL; rr++) {
        int rb0 = __ldg(&off[rr * NNODES]);
        int rb1 = (rr < NREL - 1) ? __ldg(&off[(rr + 1) * NNODES]) : NEDGES;
        int s = max(e0, rb0);
        int e = min(e1, rb1);
        for (int i = s; i < e; i++) {
            int hh = __ldg(&binh[i]);
            float w = __ldg(&binw[i]);
            uint2 v = ((const uint2*)(B16 + (size_t)hh * DIM))[lane];
            __half2* hp = (__half2*)&v;
            float2 f0 = __half22float2(hp[0]);
            float2 f1 = __half22float2(hp[1]);
            acc[rr][0] += w * f0.x; acc[rr][1] += w * f0.y;
            acc[rr][2] += w * f1.x; acc[rr][3] += w * f1.y;
        }
    }

    // node-sum vector (root path), grid-stride over nodes
    for (int t = gw; t < NNODES; t += E2_WARPS) {
        uint2 v = ((const uint2*)(B16 + (size_t)t * DIM))[lane];
        __half2* hp = (__half2*)&v;
        float2 f0 = __half22float2(hp[0]);
        float2 f1 = __half22float2(hp[1]);
        acc[8][0] += f0.x; acc[8][1] += f0.y;
        acc[8][2] += f1.x; acc[8][3] += f1.y;
    }

    for (int i = threadIdx.x; i < NVEC * DIM; i += 256) ((float*)ssum)[i] = 0.0f;
    __syncthreads();
#pragma unroll
    for (int v = 0; v < NVEC; v++)
#pragma unroll
        for (int j = 0; j < 4; j++)
            atomicAdd(&ssum[v][lane * 4 + j], acc[v][j]);
    __syncthreads();
    for (int i = threadIdx.x; i < NVEC * DIM; i += 256)
        atomicAdd(&vs[i], ((float*)ssum)[i]);
}

// ---------------- final GEMV: out[n] = b2[n] + (1/N)(vs[8]@root2 + Σ_r vs[r]@W2_r) ----------------
__global__ void k_gemv(const float* __restrict__ vs, const float* __restrict__ W2,
                       const float* __restrict__ root2, float* __restrict__ out)
{
    __shared__ float sv[DIM];
    const int z = blockIdx.x;
    const int n = threadIdx.x;
    const float* svec = (z == 0) ? (vs + 8 * DIM) : (vs + (z - 1) * DIM);
    const float* Wm   = (z == 0) ? root2 : (W2 + ((size_t)(z - 1) << 14));
    sv[n] = svec[n];
    __syncthreads();
    float s = 0.0f;
#pragma unroll 8
    for (int k = 0; k < DIM; k++)
        s += sv[k] * Wm[k * DIM + n];
    atomicAdd(&out[n], s * (1.0f / (float)NNODES));
}

__global__ void k_init_out(float* __restrict__ out, const float* __restrict__ b2) {
    out[threadIdx.x] = b2[threadIdx.x];
}

// ---------------- launch ----------------
extern "C" void kernel_launch(void* const* d_in, const int* in_sizes, int n_in,
                              void* d_out, int out_size) {
    const int*   h     = (const int*)d_in[0];
    const int*   r     = (const int*)d_in[1];
    const int*   t     = (const int*)d_in[2];
    const float* x_emb = (const float*)d_in[3];
    const float* W1    = (const float*)d_in[4];
    const float* root1 = (const float*)d_in[5];
    const float* b1    = (const float*)d_in[6];
    const float* W2    = (const float*)d_in[7];
    const float* root2 = (const float*)d_in[8];
    const float* b2    = (const float*)d_in[9];
    float* out = (float*)d_out;

    __half *M16, *A16, *B16, *WH;
    float *vs, *inv, *binw;
    int *cnt, *incl, *off, *cursor, *binh, *bsum;
    cudaGetSymbolAddress((void**)&M16,    g_M16);
    cudaGetSymbolAddress((void**)&A16,    g_A16);
    cudaGetSymbolAddress((void**)&B16,    g_B16);
    cudaGetSymbolAddress((void**)&WH,     g_WH);
    cudaGetSymbolAddress((void**)&vs,     g_vs);
    cudaGetSymbolAddress((void**)&cnt,    g_cnt);
    cudaGetSymbolAddress((void**)&incl,   g_incl);
    cudaGetSymbolAddress((void**)&off,    g_off);
    cudaGetSymbolAddress((void**)&cursor, g_cursor);
    cudaGetSymbolAddress((void**)&inv,    g_inv);
    cudaGetSymbolAddress((void**)&binh,   g_binh);
    cudaGetSymbolAddress((void**)&binw,   g_binw);
    cudaGetSymbolAddress((void**)&bsum,   g_bsum);

    const int E = NEDGES, Nn = NNODES;
    const int n2 = Nn * DIM / 2;

    // one-time resources (created on the first, uncaptured call; reused under capture)
    static cudaStream_t s2 = nullptr;
    static cudaEvent_t evFork, evCSR, evA0, evA1;
    if (!s2) {
        cudaFuncSetAttribute(k_gemmF, cudaFuncAttributeMaxDynamicSharedMemorySize, GEMM_SMEM);
        cudaStreamCreateWithFlags(&s2, cudaStreamNonBlocking);
        cudaEventCreateWithFlags(&evFork, cudaEventDisableTiming);
        cudaEventCreateWithFlags(&evCSR,  cudaEventDisableTiming);
        cudaEventCreateWithFlags(&evA0,   cudaEventDisableTiming);
        cudaEventCreateWithFlags(&evA1,   cudaEventDisableTiming);
    }

    // ---- fork: CSR build on s2, overlapping prep on main stream ----
    cudaEventRecord(evFork, 0);
    cudaStreamWaitEvent(s2, evFork, 0);
    k_zero_cnt<<<(SEG + 255) / 256, 256, 0, s2>>>(cnt, SEG);
    k_count<<<(E + 255) / 256, 256, 0, s2>>>(r, t, cnt, E);
    k_scan1<<<NSCAN_BLK, 512, 0, s2>>>(cnt, incl, bsum, SEG);
    k_scan2<<<1, 1024, 0, s2>>>(bsum, NSCAN_BLK);
    k_scan3<<<NSCAN_BLK, 512, 0, s2>>>(cnt, incl, bsum, off, cursor, inv, SEG);
    k_bin<<<(E + 255) / 256, 256, 0, s2>>>(h, r, t, cursor, inv, binh, binw, E);
    cudaEventRecord(evCSR, s2);

    // ---- main stream: prep ----
    k_wt1<<<(NZ * DIM * DIM + 255) / 256, 256>>>(W1, root1, WH);
    k_cvt16<<<(n2 + 255) / 256, 256>>>((const float2*)x_emb, (uint32_t*)A16, n2);
    k_zero_vs<<<(NVEC * DIM + 255) / 256, 256>>>(vs);
    k_init_out<<<1, DIM>>>(out, b2);

    cudaStreamWaitEvent(0, evCSR, 0);   // CSR needed from here on

    // ---- layer 1, pipelined halves: aggF(h0) -> [gemmF(h0) || aggF(h1)] -> gemmF(h1)
    k_aggF<<<H0N / 8, 256>>>(A16, off, binh, M16, 0);
    cudaEventRecord(evA0, 0);
    k_gemmF<<<G0B, 256, GEMM_SMEM>>>(A16, M16, WH, b1, B16, Nn, 0);

    cudaStreamWaitEvent(s2, evA0, 0);   // also implies prep done (evA0 after cvt16)
    k_aggF<<<H1N / 8, 256, 0, s2>>>(A16, off, binh, M16, H0N);
    cudaEventRecord(evA1, s2);

    cudaStreamWaitEvent(0, evA1, 0);
    k_gemmF<<<G1B, 256, GEMM_SMEM>>>(A16, M16, WH, b1, B16, Nn, H0N);

    // ---- layer 2: edge-centric reduction to 9 vectors, then fp32 GEMV ----
    k_edge2<<<E2_BLOCKS, 256>>>(B16, off, binh, binw, vs);
    k_gemv<<<NZ, DIM>>>(vs, W2, root2, out);
}

// round 15
// speedup vs baseline: 1.0866x; 1.0866x over previous
#include <cuda_runtime.h>
#include <cuda_fp16.h>
#include <cstdint>

// Problem constants (fixed by the reference)
#define NNODES 50000
#define NREL   8
#define DIM    128
#define NEDGES 800000
#define NZ     9                       // z=0: root path, z=1..8: relations 0..7
#define MTILE  128
#define NRB    ((NNODES + MTILE - 1) / MTILE)   // 391 row blocks
#define SEG    (NREL * NNODES)         // 400000
#define NSCAN_BLK ((SEG + 511) / 512)  // 782
#define NVEC   (NREL + 1)              // 8 relation sums + 1 node sum

// K = 9*128 = 1152, chunked by BK=64 halves (32 u32). Row stride 36 u32 (pad 4):
// ldmatrix 8 rows spaced 36 u32 -> start banks {0,4,...,28}, 4 banks/row -> conflict-free.
// Triple-buffered cp.async pipeline (depth 3).
#define NCHUNK 18
#define CSTR   36
#define A_CH   (MTILE * CSTR)          // 4608 u32 = 18432 B
#define NBUF   3
#define GEMM_SMEM (2 * NBUF * A_CH * 4)   // 110592 B (A[3] + B[3])

// layer-2 edge-centric reduction geometry
#define E2_BLOCKS 1184
#define E2_WARPS  (E2_BLOCKS * 8)                  // 9472
#define EPW       ((NEDGES + E2_WARPS - 1) / E2_WARPS)  // 85

// ---------------- scratch (static device globals; no allocation) ----------------
__device__ __half g_M16[(size_t)NREL * NNODES * DIM]; // layer-1 per-relation means (fp16)
__device__ __half g_A16[(size_t)NNODES * DIM];        // layer-1 input (fp16)
__device__ __half g_B16[(size_t)NNODES * DIM];        // layer-1 output (fp16)
__device__ __half g_WH[NZ * DIM * DIM];               // layer-1 weights [z][n][k], z=0 root
__device__ float  g_vs[NVEC * DIM];                   // layer-2 reduced vectors (fp32)
__device__ int    g_cnt[SEG];
__device__ int    g_incl[SEG];
__device__ int    g_off[SEG + 1];
__device__ int    g_cursor[SEG];
__device__ float  g_inv[SEG];
__device__ int    g_binh[NEDGES];
__device__ float  g_binw[NEDGES];
__device__ int    g_bsum[1024];

// ---------------- helpers ----------------
__device__ __forceinline__ void mma_f16(float* c, const uint32_t* a, const uint32_t* b) {
    asm volatile(
        "mma.sync.aligned.m16n8k16.row.col.f32.f16.f16.f32 "
        "{%0,%1,%2,%3}, {%4,%5,%6,%7}, {%8,%9}, {%0,%1,%2,%3};"
        : "+f"(c[0]), "+f"(c[1]), "+f"(c[2]), "+f"(c[3])
        : "r"(a[0]), "r"(a[1]), "r"(a[2]), "r"(a[3]), "r"(b[0]), "r"(b[1]));
}
__device__ __forceinline__ void ldsm_x4(uint32_t& r0, uint32_t& r1, uint32_t& r2,
                                        uint32_t& r3, uint32_t addr) {
    asm volatile("ldmatrix.sync.aligned.m8n8.x4.shared.b16 {%0,%1,%2,%3}, [%4];"
                 : "=r"(r0), "=r"(r1), "=r"(r2), "=r"(r3) : "r"(addr));
}
__device__ __forceinline__ void cp_async16(uint32_t daddr, const void* src, int srcbytes) {
    asm volatile("cp.async.cg.shared.global [%0], [%1], 16, %2;"
                 :: "r"(daddr), "l"(src), "r"(srcbytes));
}
#define CP_COMMIT() asm volatile("cp.async.commit_group;" ::: "memory")
#define CP_WAIT2()  asm volatile("cp.async.wait_group 2;" ::: "memory")
#define CP_WAIT1()  asm volatile("cp.async.wait_group 1;" ::: "memory")
#define CP_WAIT0()  asm volatile("cp.async.wait_group 0;" ::: "memory")

// ---------------- setup / binning kernels ----------------
__global__ void k_zero_cnt(int* __restrict__ cnt, int n) {
    int i = blockIdx.x * blockDim.x + threadIdx.x;
    if (i < n) cnt[i] = 0;
}
__global__ void k_count(const int* __restrict__ r, const int* __restrict__ t,
                        int* __restrict__ cnt, int E) {
    int e = blockIdx.x * blockDim.x + threadIdx.x;
    if (e < E) atomicAdd(&cnt[r[e] * NNODES + t[e]], 1);
}
__global__ void k_scan1(const int* __restrict__ cnt, int* __restrict__ incl,
                        int* __restrict__ bsum, int n) {
    __shared__ int sm[512];
    int tid = threadIdx.x;
    int gid = blockIdx.x * 512 + tid;
    sm[tid] = (gid < n) ? cnt[gid] : 0;
    __syncthreads();
#pragma unroll
    for (int d = 1; d < 512; d <<= 1) {
        int add = (tid >= d) ? sm[tid - d] : 0;
        __syncthreads();
        sm[tid] += add;
        __syncthreads();
    }
    if (gid < n) incl[gid] = sm[tid];
    if (tid == 511) bsum[blockIdx.x] = sm[511];
}
__global__ void k_scan2(int* __restrict__ bsum, int nb) {
    __shared__ int sm[1024];
    int tid = threadIdx.x;
    sm[tid] = (tid < nb) ? bsum[tid] : 0;
    __syncthreads();
#pragma unroll
    for (int d = 1; d < 1024; d <<= 1) {
        int add = (tid >= d) ? sm[tid - d] : 0;
        __syncthreads();
        sm[tid] += add;
        __syncthreads();
    }
    if (tid < nb) bsum[tid] = sm[tid];
}
__global__ void k_scan3(const int* __restrict__ cnt, const int* __restrict__ incl,
                        const int* __restrict__ bsum, int* __restrict__ off,
                        int* __restrict__ cursor, float* __restrict__ inv, int n) {
    int gid = blockIdx.x * 512 + threadIdx.x;
    if (gid >= n) return;
    int base = (blockIdx.x > 0) ? bsum[blockIdx.x - 1] : 0;
    int ex = base + incl[gid] - cnt[gid];
    off[gid] = ex;
    cursor[gid] = ex;
    inv[gid] = 1.0f / fmaxf((float)cnt[gid], 1.0f);
    if (gid == n - 1) off[n] = base + incl[gid];
}
__global__ void k_bin(const int* __restrict__ h, const int* __restrict__ r,
                      const int* __restrict__ t, int* __restrict__ cursor,
                      const float* __restrict__ inv, int* __restrict__ binh,
                      float* __restrict__ binw, int E) {
    int e = blockIdx.x * blockDim.x + threadIdx.x;
    if (e >= E) return;
    int seg = r[e] * NNODES + t[e];
    int pos = atomicAdd(&cursor[seg], 1);
    binh[pos] = h[e];
    binw[pos] = inv[seg];
}

// WH layer-1 only: [z][n][k]; z=0 -> root1, z>=1 -> W1[z-1]; transposed + fp16
__global__ void k_wt1(const float* __restrict__ W1, const float* __restrict__ root1,
                      __half* __restrict__ dst) {
    int idx = blockIdx.x * blockDim.x + threadIdx.x;
    if (idx >= NZ * DIM * DIM) return;
    int z = idx >> 14;
    int rem = idx & 16383;
    int n = rem >> 7, k = rem & 127;
    const float* src = (z == 0) ? root1 : (W1 + ((size_t)(z - 1) << 14));
    dst[idx] = __float2half_rn(src[k * DIM + n]);
}

__global__ void k_cvt16(const float2* __restrict__ in, uint32_t* __restrict__ out, int n2) {
    int i = blockIdx.x * blockDim.x + threadIdx.x;
    if (i < n2) {
        float2 v = in[i];
        __half2 hv = __floats2half2_rn(v.x, v.y);
        out[i] = *(uint32_t*)&hv;
    }
}

__global__ void k_zero_vs(float* __restrict__ vs) {
    int i = blockIdx.x * blockDim.x + threadIdx.x;
    if (i < NVEC * DIM) vs[i] = 0.0f;
}

// ---------------- layer-1 aggregate-first: M16[r][t] = mean over seg(r,t) of X16[h] ----------------
// Parallel offset preload: one L2 round for all 16 segment bounds, shfl-distributed.
__global__ __launch_bounds__(256) void k_aggF(
    const __half* __restrict__ X16, const int* __restrict__ off,
    const int* __restrict__ binh, __half* __restrict__ M16)
{
    const int wid = threadIdx.x >> 5;
    const int lane = threadIdx.x & 31;
    const int t = blockIdx.x * 8 + wid;        // NNODES % 8 == 0

    int o = 0;
    if (lane < 8)                     o = __ldg(&off[lane * NNODES + t]);
    else if (lane >= 16 && lane < 24) o = __ldg(&off[(lane - 16) * NNODES + t + 1]);

#pragma unroll
    for (int rr = 0; rr < NREL; rr++) {
        int s = __shfl_sync(0xffffffff, o, rr);
        int e = __shfl_sync(0xffffffff, o, 16 + rr);
        float4 sum = make_float4(0.f, 0.f, 0.f, 0.f);
        if (e > s) {
            for (int i = s; i < e; i++) {
                int hh = __ldg(&binh[i]);
                uint2 v = ((const uint2*)(X16 + (size_t)hh * DIM))[lane];
                __half2* hp = (__half2*)&v;
                float2 f0 = __half22float2(hp[0]);
                float2 f1 = __half22float2(hp[1]);
                sum.x += f0.x; sum.y += f0.y; sum.z += f1.x; sum.w += f1.y;
            }
            float w = 1.0f / (float)(e - s);
            sum.x *= w; sum.y *= w; sum.z *= w; sum.w *= w;
        }
        __half2 h0 = __floats2half2_rn(sum.x, sum.y);
        __half2 h1 = __floats2half2_rn(sum.z, sum.w);
        uint2 o2;
        o2.x = *(uint32_t*)&h0;
        o2.y = *(uint32_t*)&h1;
        ((uint2*)(M16 + ((size_t)rr * NNODES + t) * DIM))[lane] = o2;
    }
}

// ---------------- layer-1 fused K=1152 GEMM: B16 = relu([X | M_1..M_8] @ WH + b1) ----------------
// Triple-buffered cp.async pipeline (two chunks in flight).
__global__ __launch_bounds__(256, 2) void k_gemmF(
    const __half* __restrict__ X, const __half* __restrict__ M,
    const __half* __restrict__ WH, const float* __restrict__ bias,
    __half* __restrict__ out16, int Nn)
{
    extern __shared__ uint32_t smb[];
    uint32_t* As = smb;                        // [NBUF][A_CH]
    uint32_t* Bs = smb + NBUF * A_CH;          // [NBUF][A_CH]

    const int tid = threadIdx.x;
    const int wid = tid >> 5;
    const int lane = tid & 31;
    const int g = lane >> 2;
    const int q = lane & 3;
    const int warp_m = wid & 3;
    const int warp_n = wid >> 2;
    const int row0 = blockIdx.x * MTILE;

    const uint32_t abase = (uint32_t)__cvta_generic_to_shared(As);
    const uint32_t bbase = (uint32_t)__cvta_generic_to_shared(Bs);

    auto fill_chunk = [&](int buf, int c) {
        int z = c >> 1, hc = c & 1;
        const __half* srcA = (z == 0) ? X : (M + (size_t)(z - 1) * Nn * DIM);
        const __half* srcB = WH + ((size_t)z << 14) + hc * 64;
        uint32_t ab = abase + (uint32_t)buf * A_CH * 4;
        uint32_t bb = bbase + (uint32_t)buf * A_CH * 4;
#pragma unroll
        for (int l = 0; l < 4; l++) {
            int lin = tid + 256 * l;
            int row = lin >> 3, seg = lin & 7;
            int gr = row0 + row;
            int ok = (gr < Nn) ? 16 : 0;
            int grc = (gr < Nn) ? gr : (Nn - 1);
            cp_async16(ab + (uint32_t)(row * CSTR + seg * 4) * 4,
                       srcA + (size_t)grc * DIM + hc * 64 + seg * 8, ok);
        }
#pragma unroll
        for (int l = 0; l < 4; l++) {
            int lin = tid + 256 * l;
            int row = lin >> 3, seg = lin & 7;
            cp_async16(bb + (uint32_t)(row * CSTR + seg * 4) * 4,
                       srcB + (size_t)row * DIM + seg * 8, 16);
        }
        CP_COMMIT();
    };
    fill_chunk(0, 0);
    fill_chunk(1, 1);

    const int sub = lane >> 3;
    const int rin = lane & 7;
    uint32_t aAddr[2], bAddr[4];
#pragma unroll
    for (int mt = 0; mt < 2; mt++) {
        int row = warp_m * 32 + mt * 16 + (sub & 1) * 8 + rin;
        aAddr[mt] = abase + (uint32_t)(row * CSTR + (sub >> 1) * 4) * 4;
    }
#pragma unroll
    for (int p = 0; p < 4; p++) {
        int nrow = warp_n * 64 + p * 16 + (sub >> 1) * 8 + rin;
        bAddr[p] = bbase + (uint32_t)(nrow * CSTR + (sub & 1) * 4) * 4;
    }

    float cfrag[2][8][4];
#pragma unroll
    for (int mt = 0; mt < 2; mt++)
#pragma unroll
        for (int nt = 0; nt < 8; nt++)
#pragma unroll
            for (int i = 0; i < 4; i++) cfrag[mt][nt][i] = 0.0f;

    int buf = 0;
#pragma unroll 1
    for (int c = 0; c < NCHUNK; c++) {
        if (c < NCHUNK - 2) {
            int nb = buf + 2; if (nb >= NBUF) nb -= NBUF;
            fill_chunk(nb, c + 2);
            CP_WAIT2();
        } else if (c == NCHUNK - 2) {
            CP_WAIT1();
        } else {
            CP_WAIT0();
        }
        __syncthreads();

        const uint32_t boff = (uint32_t)buf * A_CH * 4;

#pragma unroll
        for (int ks = 0; ks < 4; ks++) {
            const uint32_t koff = boff + (uint32_t)ks * 32;
            uint32_t a[2][4];
            ldsm_x4(a[0][0], a[0][1], a[0][2], a[0][3], aAddr[0] + koff);
            ldsm_x4(a[1][0], a[1][1], a[1][2], a[1][3], aAddr[1] + koff);
            uint32_t b[8][2];
#pragma unroll
            for (int p = 0; p < 4; p++)
                ldsm_x4(b[2 * p][0], b[2 * p][1], b[2 * p + 1][0], b[2 * p + 1][1],
                        bAddr[p] + koff);
#pragma unroll
            for (int mt = 0; mt < 2; mt++)
#pragma unroll
                for (int nt = 0; nt < 8; nt++)
                    mma_f16(cfrag[mt][nt], a[mt], b[nt]);
        }
        __syncthreads();

        if (++buf >= NBUF) buf = 0;
    }

#pragma unroll
    for (int mt = 0; mt < 2; mt++)
#pragma unroll
        for (int half_ = 0; half_ < 2; half_++) {
            int row = row0 + warp_m * 32 + mt * 16 + half_ * 8 + g;
            if (row >= Nn) continue;
#pragma unroll
            for (int nt = 0; nt < 8; nt++) {
                int col = warp_n * 64 + nt * 8 + 2 * q;
                float vx = cfrag[mt][nt][half_ * 2 + 0] + bias[col];
                float vy = cfrag[mt][nt][half_ * 2 + 1] + bias[col + 1];
                __half2 hv = __floats2half2_rn(fmaxf(vx, 0.f), fmaxf(vy, 0.f));
                *(uint32_t*)&out16[(size_t)row * DIM + col] = *(uint32_t*)&hv;
            }
        }
}

// ---------------- layer-2 edge-centric reduction ----------------
// vs[r] = Σ_edges(rel r) binw[e] * B16[binh[e]];  vs[8] = Σ_t B16[t].
__global__ __launch_bounds__(256) void k_edge2(
    const __half* __restrict__ B16, const int* __restrict__ off,
    const int* __restrict__ binh, const float* __restrict__ binw,
    float* __restrict__ vs)
{
    __shared__ float ssum[NVEC][DIM];
    const int wid = threadIdx.x >> 5;
    const int lane = threadIdx.x & 31;
    const int gw = blockIdx.x * 8 + wid;

    float acc[NVEC][4];
#pragma unroll
    for (int v = 0; v < NVEC; v++)
#pragma unroll
        for (int j = 0; j < 4; j++) acc[v][j] = 0.0f;

    const int e0 = gw * EPW;
    const int e1 = min(e0 + EPW, NEDGES);

#pragma unroll
    for (int rr = 0; rr < NREL; rr++) {
        int rb0 = __ldg(&off[rr * NNODES]);
        int rb1 = (rr < NREL - 1) ? __ldg(&off[(rr + 1) * NNODES]) : NEDGES;
        int s = max(e0, rb0);
        int e = min(e1, rb1);
        for (int i = s; i < e; i++) {
            int hh = __ldg(&binh[i]);
            float w = __ldg(&binw[i]);
            uint2 v = ((const uint2*)(B16 + (size_t)hh * DIM))[lane];
            __half2* hp = (__half2*)&v;
            float2 f0 = __half22float2(hp[0]);
            float2 f1 = __half22float2(hp[1]);
            acc[rr][0] += w * f0.x; acc[rr][1] += w * f0.y;
            acc[rr][2] += w * f1.x; acc[rr][3] += w * f1.y;
        }
    }

    // node-sum vector (root path), grid-stride over nodes
    for (int t = gw; t < NNODES; t += E2_WARPS) {
        uint2 v = ((const uint2*)(B16 + (size_t)t * DIM))[lane];
        __half2* hp = (__half2*)&v;
        float2 f0 = __half22float2(hp[0]);
        float2 f1 = __half22float2(hp[1]);
        acc[8][0] += f0.x; acc[8][1] += f0.y;
        acc[8][2] += f1.x; acc[8][3] += f1.y;
    }

    for (int i = threadIdx.x; i < NVEC * DIM; i += 256) ((float*)ssum)[i] = 0.0f;
    __syncthreads();
#pragma unroll
    for (int v = 0; v < NVEC; v++)
#pragma unroll
        for (int j = 0; j < 4; j++)
            atomicAdd(&ssum[v][lane * 4 + j], acc[v][j]);
    __syncthreads();
    for (int i = threadIdx.x; i < NVEC * DIM; i += 256)
        atomicAdd(&vs[i], ((float*)ssum)[i]);
}

// ---------------- final GEMV: out[n] = b2[n] + (1/N)(vs[8]@root2 + Σ_r vs[r]@W2_r) ----------------
__global__ void k_gemv(const float* __restrict__ vs, const float* __restrict__ W2,
                       const float* __restrict__ root2, float* __restrict__ out)
{
    __shared__ float sv[DIM];
    const int z = blockIdx.x;
    const int n = threadIdx.x;
    const float* svec = (z == 0) ? (vs + 8 * DIM) : (vs + (z - 1) * DIM);
    const float* Wm   = (z == 0) ? root2 : (W2 + ((size_t)(z - 1) << 14));
    sv[n] = svec[n];
    __syncthreads();
    float s = 0.0f;
#pragma unroll 8
    for (int k = 0; k < DIM; k++)
        s += sv[k] * Wm[k * DIM + n];
    atomicAdd(&out[n], s * (1.0f / (float)NNODES));
}

__global__ void k_init_out(float* __restrict__ out, const float* __restrict__ b2) {
    out[threadIdx.x] = b2[threadIdx.x];
}

// ---------------- launch ----------------
extern "C" void kernel_launch(void* const* d_in, const int* in_sizes, int n_in,
                              void* d_out, int out_size) {
    const int*   h     = (const int*)d_in[0];
    const int*   r     = (const int*)d_in[1];
    const int*   t     = (const int*)d_in[2];
    const float* x_emb = (const float*)d_in[3];
    const float* W1    = (const float*)d_in[4];
    const float* root1 = (const float*)d_in[5];
    const float* b1    = (const float*)d_in[6];
    const float* W2    = (const float*)d_in[7];
    const float* root2 = (const float*)d_in[8];
    const float* b2    = (const float*)d_in[9];
    float* out = (float*)d_out;

    __half *M16, *A16, *B16, *WH;
    float *vs, *inv, *binw;
    int *cnt, *incl, *off, *cursor, *binh, *bsum;
    cudaGetSymbolAddress((void**)&M16,    g_M16);
    cudaGetSymbolAddress((void**)&A16,    g_A16);
    cudaGetSymbolAddress((void**)&B16,    g_B16);
    cudaGetSymbolAddress((void**)&WH,     g_WH);
    cudaGetSymbolAddress((void**)&vs,     g_vs);
    cudaGetSymbolAddress((void**)&cnt,    g_cnt);
    cudaGetSymbolAddress((void**)&incl,   g_incl);
    cudaGetSymbolAddress((void**)&off,    g_off);
    cudaGetSymbolAddress((void**)&cursor, g_cursor);
    cudaGetSymbolAddress((void**)&inv,    g_inv);
    cudaGetSymbolAddress((void**)&binh,   g_binh);
    cudaGetSymbolAddress((void**)&binw,   g_binw);
    cudaGetSymbolAddress((void**)&bsum,   g_bsum);

    const int E = NEDGES, Nn = NNODES;
    const int n2 = Nn * DIM / 2;
    const int agg_blocks = Nn / 8;   // 6250

    // one-time resources (created on the first, uncaptured call; reused under capture)
    static cudaStream_t s2 = nullptr;
    static cudaEvent_t evFork, evCSR;
    if (!s2) {
        cudaFuncSetAttribute(k_gemmF, cudaFuncAttributeMaxDynamicSharedMemorySize, GEMM_SMEM);
        cudaStreamCreateWithFlags(&s2, cudaStreamNonBlocking);
        cudaEventCreateWithFlags(&evFork, cudaEventDisableTiming);
        cudaEventCreateWithFlags(&evCSR,  cudaEventDisableTiming);
    }

    // ---- fork: CSR build on s2, overlapping prep on main stream ----
    cudaEventRecord(evFork, 0);
    cudaStreamWaitEvent(s2, evFork, 0);
    k_zero_cnt<<<(SEG + 255) / 256, 256, 0, s2>>>(cnt, SEG);
    k_count<<<(E + 255) / 256, 256, 0, s2>>>(r, t, cnt, E);
    k_scan1<<<NSCAN_BLK, 512, 0, s2>>>(cnt, incl, bsum, SEG);
    k_scan2<<<1, 1024, 0, s2>>>(bsum, NSCAN_BLK);
    k_scan3<<<NSCAN_BLK, 512, 0, s2>>>(cnt, incl, bsum, off, cursor, inv, SEG);
    k_bin<<<(E + 255) / 256, 256, 0, s2>>>(h, r, t, cursor, inv, binh, binw, E);
    cudaEventRecord(evCSR, s2);

    // ---- main stream: prep ----
    k_wt1<<<(NZ * DIM * DIM + 255) / 256, 256>>>(W1, root1, WH);
    k_cvt16<<<(n2 + 255) / 256, 256>>>((const float2*)x_emb, (uint32_t*)A16, n2);
    k_zero_vs<<<(NVEC * DIM + 255) / 256, 256>>>(vs);
    k_init_out<<<1, DIM>>>(out, b2);

    cudaStreamWaitEvent(0, evCSR, 0);   // CSR needed from here on

    // ---- layer 1: aggregate-first, fused K=1152 GEMM (relu -> B16) ----
    k_aggF<<<agg_blocks, 256>>>(A16, off, binh, M16);
    k_gemmF<<<NRB, 256, GEMM_SMEM>>>(A16, M16, WH, b1, B16, Nn);

    // ---- layer 2: edge-centric reduction to 9 vectors, then fp32 GEMV ----
    k_edge2<<<E2_BLOCKS, 256>>>(B16, off, binh, binw, vs);
    k_gemv<<<NZ, DIM>>>(vs, W2, root2, out);
}